// round 3
// baseline (speedup 1.0000x reference)
#include <cuda_runtime.h>
#include <cuda_bf16.h>
#include <cstdint>
#include <cstddef>

// ---------------------------------------------------------------------------
// QLoRABigNet: 18 sequential layers of y = x @ W_eff^T + bias (+relu / +residual / LN)
// where W_eff = dequant_int4(qw, scales) + lora_b @ lora_a  (precomputed per replay).
//
// Numerics: split-bf16 "3-MMA" emulation of fp32 GEMM:
//   x = x_hi + x_lo (bf16 pair), W = W_hi + W_lo (bf16 pair)
//   y ≈ x_hi*W_hi + x_lo*W_hi + x_hi*W_lo   (fp32 accumulate)
// Per-layer norm-relative error ~3e-6 -> ~1e-5 over 18 layers. Well under 1e-3.
// ---------------------------------------------------------------------------

#define NL    18
#define DIMV  1024
#define BV    32768
#define NGRP  64          // DIM / group_size

// ---- scratch (device globals: allocation-free contract) --------------------
__device__ __nv_bfloat16 g_Whi[(size_t)NL * DIMV * DIMV];
__device__ __nv_bfloat16 g_Wlo[(size_t)NL * DIMV * DIMV];
__device__ __nv_bfloat16 g_ahi0[(size_t)BV * DIMV];
__device__ __nv_bfloat16 g_alo0[(size_t)BV * DIMV];
__device__ __nv_bfloat16 g_ahi1[(size_t)BV * DIMV];
__device__ __nv_bfloat16 g_alo1[(size_t)BV * DIMV];
__device__ float         g_ybuf[(size_t)BV * DIMV];
__device__ float         g_h[(size_t)BV * DIMV];

// ---------------------------------------------------------------------------
// Prepass: W_eff[l][o][k] = qw*scale + (B@A)[o][k]; split into bf16 hi/lo.
// Tile 64x64 per CTA, K=32 lora contraction via smem.
// ---------------------------------------------------------------------------
__global__ __launch_bounds__(256) void prep_w_kernel(
    const int* __restrict__ qw, const float* __restrict__ sc,
    const float* __restrict__ la, const float* __restrict__ lb,
    __nv_bfloat16* __restrict__ Whi, __nv_bfloat16* __restrict__ Wlo)
{
    int l  = blockIdx.z;
    int o0 = blockIdx.y * 64;
    int k0 = blockIdx.x * 64;
    int tid = threadIdx.x;

    __shared__ float sLb[64][32];   // [o][r]
    __shared__ float sLa[32][64];   // [r][k]

    const float* lbp = lb + (size_t)l * DIMV * 32;
    const float* lap = la + (size_t)l * 32 * DIMV;

#pragma unroll
    for (int i = 0; i < 8; i++) {
        int off = tid + i * 256;            // 0..2047
        int o = off >> 5, r = off & 31;
        sLb[o][r] = lbp[(size_t)(o0 + o) * 32 + r];
        int r2 = off >> 6, k = off & 63;
        sLa[r2][k] = lap[(size_t)r2 * DIMV + k0 + k];
    }
    __syncthreads();

    int to = tid >> 4, tk = tid & 15;
    float m[4][4];
#pragma unroll
    for (int i = 0; i < 4; i++)
#pragma unroll
        for (int j = 0; j < 4; j++) m[i][j] = 0.f;

#pragma unroll 8
    for (int r = 0; r < 32; r++) {
        float av[4], bv[4];
#pragma unroll
        for (int j = 0; j < 4; j++) av[j] = sLa[r][tk * 4 + j];
#pragma unroll
        for (int i = 0; i < 4; i++) bv[i] = sLb[to * 4 + i][r];
#pragma unroll
        for (int i = 0; i < 4; i++)
#pragma unroll
            for (int j = 0; j < 4; j++) m[i][j] += bv[i] * av[j];
    }

#pragma unroll
    for (int i = 0; i < 4; i++) {
        int o = o0 + to * 4 + i;
        const int*   qrow = qw + ((size_t)l * DIMV + o) * DIMV + k0;
        const float* srow = sc + ((size_t)l * DIMV + o) * NGRP;
#pragma unroll
        for (int j = 0; j < 4; j++) {
            int k = k0 + tk * 4 + j;
            float wv = (float)qrow[tk * 4 + j] * srow[k >> 4] + m[i][j];
            size_t idx = ((size_t)l * DIMV + o) * DIMV + k;
            __nv_bfloat16 h = __float2bfloat16(wv);
            Whi[idx] = h;
            Wlo[idx] = __float2bfloat16(wv - __bfloat162float(h));
        }
    }
}

// ---------------------------------------------------------------------------
// Split fp32 input into bf16 hi/lo pair.
// ---------------------------------------------------------------------------
__global__ __launch_bounds__(256) void split_x_kernel(
    const float* __restrict__ x, __nv_bfloat16* __restrict__ hi,
    __nv_bfloat16* __restrict__ lo)
{
    size_t i = (size_t)blockIdx.x * 256 + threadIdx.x;
    float v = x[i];
    __nv_bfloat16 h = __float2bfloat16(v);
    hi[i] = h;
    lo[i] = __float2bfloat16(v - __bfloat162float(h));
}

// ---------------------------------------------------------------------------
// MMA helpers (mma.sync m16n8k16 bf16, ldmatrix)
// ---------------------------------------------------------------------------
__device__ __forceinline__ void ldsm4(uint32_t* r, const void* p) {
    uint32_t a = (uint32_t)__cvta_generic_to_shared(p);
    asm volatile("ldmatrix.sync.aligned.m8n8.x4.shared.b16 {%0,%1,%2,%3}, [%4];\n"
                 : "=r"(r[0]), "=r"(r[1]), "=r"(r[2]), "=r"(r[3]) : "r"(a));
}
__device__ __forceinline__ void ldsm2(uint32_t* r, const void* p) {
    uint32_t a = (uint32_t)__cvta_generic_to_shared(p);
    asm volatile("ldmatrix.sync.aligned.m8n8.x2.shared.b16 {%0,%1}, [%2];\n"
                 : "=r"(r[0]), "=r"(r[1]) : "r"(a));
}
__device__ __forceinline__ void mma16816(float* c, const uint32_t* a, const uint32_t* b) {
    asm volatile(
        "mma.sync.aligned.m16n8k16.row.col.f32.bf16.bf16.f32 "
        "{%0,%1,%2,%3}, {%4,%5,%6,%7}, {%8,%9}, {%0,%1,%2,%3};\n"
        : "+f"(c[0]), "+f"(c[1]), "+f"(c[2]), "+f"(c[3])
        : "r"(a[0]), "r"(a[1]), "r"(a[2]), "r"(a[3]), "r"(b[0]), "r"(b[1]));
}

// ---------------------------------------------------------------------------
// Main GEMM: C[BV,DIMV] = X @ W^T, X split hi/lo, W split hi/lo (3 MMAs / frag).
// CTA tile 128x128, k-tile 16, double-buffered smem (exactly 48KB).
// mode 0: out = relu(acc + bias) -> bf16 hi/lo act buffers (next layer input)
// mode 1: out = acc + bias + hin -> fp32 fout (pre-LN residual, or final output)
// ---------------------------------------------------------------------------
#define BM 128
#define BN 128
#define KPAD 24

__global__ __launch_bounds__(256) void gemm_kernel(
    const __nv_bfloat16* __restrict__ Xhi, const __nv_bfloat16* __restrict__ Xlo,
    const __nv_bfloat16* __restrict__ Whi, const __nv_bfloat16* __restrict__ Wlo,
    const float* __restrict__ bias, int mode,
    const float* __restrict__ hin, float* __restrict__ fout,
    __nv_bfloat16* __restrict__ Ohi, __nv_bfloat16* __restrict__ Olo)
{
    __shared__ __nv_bfloat16 sXh[2][BM][KPAD];
    __shared__ __nv_bfloat16 sXl[2][BM][KPAD];
    __shared__ __nv_bfloat16 sWh[2][BN][KPAD];
    __shared__ __nv_bfloat16 sWl[2][BN][KPAD];

    const int tid  = threadIdx.x;
    const int warp = tid >> 5, lane = tid & 31;
    const int wm = warp >> 2, wn = warp & 3;      // 2 x 4 warp grid, 64x32 per warp
    const int m0 = blockIdx.y * BM, n0 = blockIdx.x * BN;

    const int lrow = tid >> 1;
    const int lcol = (tid & 1) * 8;

    const __nv_bfloat16* gxh = Xhi + (size_t)(m0 + lrow) * DIMV + lcol;
    const __nv_bfloat16* gxl = Xlo + (size_t)(m0 + lrow) * DIMV + lcol;
    const __nv_bfloat16* gwh = Whi + (size_t)(n0 + lrow) * DIMV + lcol;
    const __nv_bfloat16* gwl = Wlo + (size_t)(n0 + lrow) * DIMV + lcol;

    // prologue: k-tile 0 -> buffer 0
    {
        uint4 a = *(const uint4*)gxh;
        uint4 b = *(const uint4*)gxl;
        uint4 c = *(const uint4*)gwh;
        uint4 d = *(const uint4*)gwl;
        *(uint4*)&sXh[0][lrow][lcol] = a;
        *(uint4*)&sXl[0][lrow][lcol] = b;
        *(uint4*)&sWh[0][lrow][lcol] = c;
        *(uint4*)&sWl[0][lrow][lcol] = d;
    }
    __syncthreads();

    float acc[4][4][4];
#pragma unroll
    for (int i = 0; i < 4; i++)
#pragma unroll
        for (int j = 0; j < 4; j++)
#pragma unroll
            for (int q = 0; q < 4; q++) acc[i][j][q] = 0.f;

    // ldmatrix lane addressing (loop invariant)
    const int mi = lane >> 3, rr = lane & 7;
    const int a_r = wm * 64 + (mi & 1) * 8 + rr;
    const int a_c = (mi >> 1) * 8;
    const int li  = lane & 15;
    const int b_r = wn * 32 + (li & 7);
    const int b_c = (li >> 3) * 8;

    for (int kt = 0; kt < 64; ++kt) {
        const int cur = kt & 1;
        uint4 pa, pb, pc, pd;
        if (kt < 63) {
            int ko = (kt + 1) * 16;
            pa = *(const uint4*)(gxh + ko);
            pb = *(const uint4*)(gxl + ko);
            pc = *(const uint4*)(gwh + ko);
            pd = *(const uint4*)(gwl + ko);
        }

        uint32_t fxh[4][4], fxl[4][4], fwh[4][2], fwl[4][2];
#pragma unroll
        for (int mf = 0; mf < 4; mf++) {
            ldsm4(fxh[mf], &sXh[cur][a_r + mf * 16][a_c]);
            ldsm4(fxl[mf], &sXl[cur][a_r + mf * 16][a_c]);
        }
#pragma unroll
        for (int nf = 0; nf < 4; nf++) {
            ldsm2(fwh[nf], &sWh[cur][b_r + nf * 8][b_c]);
            ldsm2(fwl[nf], &sWl[cur][b_r + nf * 8][b_c]);
        }
#pragma unroll
        for (int mf = 0; mf < 4; mf++)
#pragma unroll
            for (int nf = 0; nf < 4; nf++) {
                mma16816(acc[mf][nf], fxh[mf], fwh[nf]);
                mma16816(acc[mf][nf], fxl[mf], fwh[nf]);
                mma16816(acc[mf][nf], fxh[mf], fwl[nf]);
            }

        if (kt < 63) {
            const int nxt = cur ^ 1;
            *(uint4*)&sXh[nxt][lrow][lcol] = pa;
            *(uint4*)&sXl[nxt][lrow][lcol] = pb;
            *(uint4*)&sWh[nxt][lrow][lcol] = pc;
            *(uint4*)&sWl[nxt][lrow][lcol] = pd;
        }
        __syncthreads();
    }

    // epilogue
#pragma unroll
    for (int mf = 0; mf < 4; mf++) {
#pragma unroll
        for (int nf = 0; nf < 4; nf++) {
            const float* c = acc[mf][nf];
            int row0 = m0 + wm * 64 + mf * 16 + (lane >> 2);
            int row1 = row0 + 8;
            int n = n0 + wn * 32 + nf * 8 + 2 * (lane & 3);
            float bn0 = bias[n], bn1 = bias[n + 1];
            size_t o0 = (size_t)row0 * DIMV + n;
            size_t o1 = (size_t)row1 * DIMV + n;
            if (mode == 0) {
                float v00 = fmaxf(c[0] + bn0, 0.f), v01 = fmaxf(c[1] + bn1, 0.f);
                float v10 = fmaxf(c[2] + bn0, 0.f), v11 = fmaxf(c[3] + bn1, 0.f);
                __nv_bfloat162 h2, l2;
                h2.x = __float2bfloat16(v00); l2.x = __float2bfloat16(v00 - __bfloat162float(h2.x));
                h2.y = __float2bfloat16(v01); l2.y = __float2bfloat16(v01 - __bfloat162float(h2.y));
                *(__nv_bfloat162*)(Ohi + o0) = h2;
                *(__nv_bfloat162*)(Olo + o0) = l2;
                h2.x = __float2bfloat16(v10); l2.x = __float2bfloat16(v10 - __bfloat162float(h2.x));
                h2.y = __float2bfloat16(v11); l2.y = __float2bfloat16(v11 - __bfloat162float(h2.y));
                *(__nv_bfloat162*)(Ohi + o1) = h2;
                *(__nv_bfloat162*)(Olo + o1) = l2;
            } else {
                float2 hv0 = *(const float2*)(hin + o0);
                float2 hv1 = *(const float2*)(hin + o1);
                float2 r0v; r0v.x = c[0] + bn0 + hv0.x; r0v.y = c[1] + bn1 + hv0.y;
                float2 r1v; r1v.x = c[2] + bn0 + hv1.x; r1v.y = c[3] + bn1 + hv1.y;
                *(float2*)(fout + o0) = r0v;
                *(float2*)(fout + o1) = r1v;
            }
        }
    }
}

// ---------------------------------------------------------------------------
// LayerNorm over rows of t; writes h (fp32, next residual base) + bf16 hi/lo act.
// ---------------------------------------------------------------------------
__global__ __launch_bounds__(256) void ln_kernel(
    const float* __restrict__ t, const float* __restrict__ g,
    const float* __restrict__ bb, float* __restrict__ hout,
    __nv_bfloat16* __restrict__ Ohi, __nv_bfloat16* __restrict__ Olo)
{
    int row = blockIdx.x;
    int tid = threadIdx.x;
    const float* tr = t + (size_t)row * DIMV;

    float v[4];
#pragma unroll
    for (int i = 0; i < 4; i++) v[i] = tr[tid + 256 * i];

    float s = v[0] + v[1] + v[2] + v[3];
#pragma unroll
    for (int o = 16; o > 0; o >>= 1) s += __shfl_xor_sync(0xffffffffu, s, o);

    __shared__ float red[8];
    int w = tid >> 5, ln = tid & 31;
    if (ln == 0) red[w] = s;
    __syncthreads();
    float tot = 0.f;
#pragma unroll
    for (int i = 0; i < 8; i++) tot += red[i];
    float mu = tot * (1.0f / 1024.0f);

    float sq = 0.f;
#pragma unroll
    for (int i = 0; i < 4; i++) { float d = v[i] - mu; sq += d * d; }
#pragma unroll
    for (int o = 16; o > 0; o >>= 1) sq += __shfl_xor_sync(0xffffffffu, sq, o);
    __syncthreads();
    if (ln == 0) red[w] = sq;
    __syncthreads();
    float vtot = 0.f;
#pragma unroll
    for (int i = 0; i < 8; i++) vtot += red[i];
    float rs = rsqrtf(vtot * (1.0f / 1024.0f) + 1e-5f);

#pragma unroll
    for (int i = 0; i < 4; i++) {
        int col = tid + 256 * i;
        float o = (v[i] - mu) * rs * g[col] + bb[col];
        size_t idx = (size_t)row * DIMV + col;
        hout[idx] = o;
        __nv_bfloat16 h = __float2bfloat16(o);
        Ohi[idx] = h;
        Olo[idx] = __float2bfloat16(o - __bfloat162float(h));
    }
}

// ---------------------------------------------------------------------------
// Host: 1 prepass + 1 split + 18 GEMMs + 5 LN launches, all default stream.
// ---------------------------------------------------------------------------
extern "C" void kernel_launch(void* const* d_in, const int* in_sizes, int n_in,
                              void* d_out, int out_size)
{
    const float* x      = (const float*)d_in[0];
    const int*   qw     = (const int*)d_in[1];
    const float* scales = (const float*)d_in[2];
    const float* bias   = (const float*)d_in[3];
    const float* la     = (const float*)d_in[4];
    const float* lb     = (const float*)d_in[5];
    const float* lng    = (const float*)d_in[6];
    const float* lnb    = (const float*)d_in[7];
    float* out = (float*)d_out;

    void* p;
    cudaGetSymbolAddress(&p, g_Whi);  __nv_bfloat16* Whi  = (__nv_bfloat16*)p;
    cudaGetSymbolAddress(&p, g_Wlo);  __nv_bfloat16* Wlo  = (__nv_bfloat16*)p;
    cudaGetSymbolAddress(&p, g_ahi0); __nv_bfloat16* Ahi0 = (__nv_bfloat16*)p;
    cudaGetSymbolAddress(&p, g_alo0); __nv_bfloat16* Alo0 = (__nv_bfloat16*)p;
    cudaGetSymbolAddress(&p, g_ahi1); __nv_bfloat16* Ahi1 = (__nv_bfloat16*)p;
    cudaGetSymbolAddress(&p, g_alo1); __nv_bfloat16* Alo1 = (__nv_bfloat16*)p;
    cudaGetSymbolAddress(&p, g_ybuf); float* Ybuf = (float*)p;
    cudaGetSymbolAddress(&p, g_h);    float* Hbuf = (float*)p;

    __nv_bfloat16* ahi[2] = {Ahi0, Ahi1};
    __nv_bfloat16* alo[2] = {Alo0, Alo1};

    prep_w_kernel<<<dim3(16, 16, NL), 256>>>(qw, scales, la, lb, Whi, Wlo);
    split_x_kernel<<<(BV * DIMV) / 256, 256>>>(x, ahi[0], alo[0]);

    for (int l = 0; l < NL; l++) {
        int ib = l & 1, ob = (l + 1) & 1;
        const __nv_bfloat16* wh = Whi + (size_t)l * DIMV * DIMV;
        const __nv_bfloat16* wl = Wlo + (size_t)l * DIMV * DIMV;
        const float* bl = bias + (size_t)l * DIMV;

        if (l % 3 != 2) {
            gemm_kernel<<<dim3(8, 256), 256>>>(ahi[ib], alo[ib], wh, wl, bl,
                                               0, nullptr, nullptr,
                                               ahi[ob], alo[ob]);
        } else {
            const float* hin = (l == 2) ? x : Hbuf;
            float* fo = (l == NL - 1) ? out : Ybuf;
            gemm_kernel<<<dim3(8, 256), 256>>>(ahi[ib], alo[ib], wh, wl, bl,
                                               1, hin, fo, nullptr, nullptr);
            if (l != NL - 1) {
                int blk = l / 3;
                ln_kernel<<<BV, 256>>>(Ybuf, lng + (size_t)blk * DIMV,
                                       lnb + (size_t)blk * DIMV, Hbuf,
                                       ahi[ob], alo[ob]);
            }
        }
    }
}

// round 5
// speedup vs baseline: 1.1147x; 1.1147x over previous
#include <cuda_runtime.h>
#include <cuda_bf16.h>
#include <cstdint>
#include <cstddef>

// ---------------------------------------------------------------------------
// QLoRABigNet, mma.sync path (tcgen05 unavailable: harness PTX target is
// compute_103 which rejects sm_103a-only instructions).
// 18 layers of y = x @ W_eff^T + bias (+relu / +residual / LN).
// W_eff = dequant_int4 + lora_b@lora_a precomputed; split-bf16 3-MMA numerics:
//   y ~= x_hi*W_hi + x_lo*W_hi + x_hi*W_lo  (fp32 accum), err ~3e-5 total.
// GEMM: CTA 256x128, warp tile 64x64, K-chunk 32, 3-stage cp.async pipeline.
// ---------------------------------------------------------------------------

#define NL    18
#define DIMV  1024
#define BV    32768
#define NGRP  64

#define TM 256
#define TN 128
#define KC 32
#define NCHUNK (DIMV / KC)       // 32

// smem stage layout (bytes). Row stride = 40 elems (80B) -> conflict-free ldsm.
#define ROWB 80
#define OFF_AHI 0
#define OFF_ALO 20480            // 256*80
#define OFF_BHI 40960
#define OFF_BLO 51200            // + 128*80
#define STAGE_BYTES 61440
#define NSTAGE 3
#define SMEM_TOTAL (NSTAGE * STAGE_BYTES)   // 184320

// ---- scratch (device globals: allocation-free contract) --------------------
__device__ __nv_bfloat16 g_Whi[(size_t)NL * DIMV * DIMV];
__device__ __nv_bfloat16 g_Wlo[(size_t)NL * DIMV * DIMV];
__device__ __nv_bfloat16 g_ahi0[(size_t)BV * DIMV];
__device__ __nv_bfloat16 g_alo0[(size_t)BV * DIMV];
__device__ __nv_bfloat16 g_ahi1[(size_t)BV * DIMV];
__device__ __nv_bfloat16 g_alo1[(size_t)BV * DIMV];
__device__ float         g_ybuf[(size_t)BV * DIMV];
__device__ float         g_h[(size_t)BV * DIMV];

// ---------------------------------------------------------------------------
// PTX helpers
// ---------------------------------------------------------------------------
__device__ __forceinline__ void ldsm4(uint32_t* r, uint32_t a) {
    asm volatile("ldmatrix.sync.aligned.m8n8.x4.shared.b16 {%0,%1,%2,%3}, [%4];\n"
                 : "=r"(r[0]), "=r"(r[1]), "=r"(r[2]), "=r"(r[3]) : "r"(a));
}
__device__ __forceinline__ void mma16816(float* c, const uint32_t* a, const uint32_t* b) {
    asm volatile(
        "mma.sync.aligned.m16n8k16.row.col.f32.bf16.bf16.f32 "
        "{%0,%1,%2,%3}, {%4,%5,%6,%7}, {%8,%9}, {%0,%1,%2,%3};\n"
        : "+f"(c[0]), "+f"(c[1]), "+f"(c[2]), "+f"(c[3])
        : "r"(a[0]), "r"(a[1]), "r"(a[2]), "r"(a[3]), "r"(b[0]), "r"(b[1]));
}
__device__ __forceinline__ void cpa16(uint32_t dst, const void* src) {
    asm volatile("cp.async.cg.shared.global [%0], [%1], 16;" :: "r"(dst), "l"(src));
}
__device__ __forceinline__ void cp_commit() {
    asm volatile("cp.async.commit_group;" ::: "memory");
}

// ---------------------------------------------------------------------------
// Prepass: W_eff = qw*scale + B@A, split bf16 hi/lo. (validated in R3)
// ---------------------------------------------------------------------------
__global__ __launch_bounds__(256) void prep_w_kernel(
    const int* __restrict__ qw, const float* __restrict__ sc,
    const float* __restrict__ la, const float* __restrict__ lb,
    __nv_bfloat16* __restrict__ Whi, __nv_bfloat16* __restrict__ Wlo)
{
    int l  = blockIdx.z;
    int o0 = blockIdx.y * 64;
    int k0 = blockIdx.x * 64;
    int tid = threadIdx.x;

    __shared__ float sLb[64][32];
    __shared__ float sLa[32][64];

    const float* lbp = lb + (size_t)l * DIMV * 32;
    const float* lap = la + (size_t)l * 32 * DIMV;

#pragma unroll
    for (int i = 0; i < 8; i++) {
        int off = tid + i * 256;
        int o = off >> 5, r = off & 31;
        sLb[o][r] = lbp[(size_t)(o0 + o) * 32 + r];
        int r2 = off >> 6, k = off & 63;
        sLa[r2][k] = lap[(size_t)r2 * DIMV + k0 + k];
    }
    __syncthreads();

    int to = tid >> 4, tk = tid & 15;
    float m[4][4];
#pragma unroll
    for (int i = 0; i < 4; i++)
#pragma unroll
        for (int j = 0; j < 4; j++) m[i][j] = 0.f;

#pragma unroll 8
    for (int r = 0; r < 32; r++) {
        float av[4], bv[4];
#pragma unroll
        for (int j = 0; j < 4; j++) av[j] = sLa[r][tk * 4 + j];
#pragma unroll
        for (int i = 0; i < 4; i++) bv[i] = sLb[to * 4 + i][r];
#pragma unroll
        for (int i = 0; i < 4; i++)
#pragma unroll
            for (int j = 0; j < 4; j++) m[i][j] += bv[i] * av[j];
    }

#pragma unroll
    for (int i = 0; i < 4; i++) {
        int o = o0 + to * 4 + i;
        const int*   qrow = qw + ((size_t)l * DIMV + o) * DIMV + k0;
        const float* srow = sc + ((size_t)l * DIMV + o) * NGRP;
#pragma unroll
        for (int j = 0; j < 4; j++) {
            int k = k0 + tk * 4 + j;
            float wv = (float)qrow[tk * 4 + j] * srow[k >> 4] + m[i][j];
            size_t idx = ((size_t)l * DIMV + o) * DIMV + k;
            __nv_bfloat16 h = __float2bfloat16(wv);
            Whi[idx] = h;
            Wlo[idx] = __float2bfloat16(wv - __bfloat162float(h));
        }
    }
}

__global__ __launch_bounds__(256) void split_x_kernel(
    const float* __restrict__ x, __nv_bfloat16* __restrict__ hi,
    __nv_bfloat16* __restrict__ lo)
{
    size_t i = (size_t)blockIdx.x * 256 + threadIdx.x;
    float v = x[i];
    __nv_bfloat16 h = __float2bfloat16(v);
    hi[i] = h;
    lo[i] = __float2bfloat16(v - __bfloat162float(h));
}

// ---------------------------------------------------------------------------
// GEMM: C[BV,DIMV] = X @ W^T. grid (DIMV/TN, BV/TM) = (8, 128), 256 thr.
// mode 0: out = relu(acc+bias) -> bf16 hi/lo ; mode 1: out = acc+bias+hin fp32
// ---------------------------------------------------------------------------
__device__ __forceinline__ void load_chunk(
    uint32_t sb, int s, int kc, int tid, int m0, int n0,
    const __nv_bfloat16* __restrict__ Xhi, const __nv_bfloat16* __restrict__ Xlo,
    const __nv_bfloat16* __restrict__ Whi, const __nv_bfloat16* __restrict__ Wlo)
{
    const uint32_t st = sb + (uint32_t)s * STAGE_BYTES;
    const int kbase = kc * KC;
    // A: 256 rows x 32 elems; 4 x 16B per thread (x2 for hi/lo)
#pragma unroll
    for (int i = 0; i < 4; i++) {
        int idx = i * 256 + tid;
        int row = idx >> 2, seg = idx & 3;
        uint32_t off = (uint32_t)(row * ROWB + seg * 16);
        const size_t gsrc = (size_t)(m0 + row) * DIMV + kbase + seg * 8;
        cpa16(st + OFF_AHI + off, Xhi + gsrc);
        cpa16(st + OFF_ALO + off, Xlo + gsrc);
    }
    // B: 128 rows x 32 elems; 2 x 16B per thread (x2 for hi/lo)
#pragma unroll
    for (int i = 0; i < 2; i++) {
        int idx = i * 256 + tid;
        int row = idx >> 2, seg = idx & 3;
        uint32_t off = (uint32_t)(row * ROWB + seg * 16);
        const size_t gsrc = (size_t)(n0 + row) * DIMV + kbase + seg * 8;
        cpa16(st + OFF_BHI + off, Whi + gsrc);
        cpa16(st + OFF_BLO + off, Wlo + gsrc);
    }
    cp_commit();
}

__global__ __launch_bounds__(256, 1) void gemm_kernel(
    const __nv_bfloat16* __restrict__ Xhi, const __nv_bfloat16* __restrict__ Xlo,
    const __nv_bfloat16* __restrict__ Whi, const __nv_bfloat16* __restrict__ Wlo,
    const float* __restrict__ bias, int mode,
    const float* __restrict__ hin, float* __restrict__ fout,
    __nv_bfloat16* __restrict__ Ohi, __nv_bfloat16* __restrict__ Olo)
{
    extern __shared__ __align__(128) char smem[];
    const uint32_t sb = (uint32_t)__cvta_generic_to_shared(smem);

    const int tid = threadIdx.x, warp = tid >> 5, lane = tid & 31;
    const int wm = warp >> 1, wn = warp & 1;         // 4 x 2 warp grid, 64x64 tile
    const int m0 = blockIdx.y * TM, n0 = blockIdx.x * TN;

    // ldmatrix per-lane addressing (bytes, relative to stage base)
    const int mi = lane >> 3, rr = lane & 7;
    const uint32_t a_base = (uint32_t)((wm * 64 + (mi & 1) * 8 + rr) * ROWB
                                       + ((mi >> 1) * 8) * 2);
    const uint32_t b_base = (uint32_t)((wn * 64 + ((lane >> 4) << 3) + (lane & 7)) * ROWB
                                       + (((lane >> 3) & 1) * 8) * 2);

    // prologue: chunks 0,1
    load_chunk(sb, 0, 0, tid, m0, n0, Xhi, Xlo, Whi, Wlo);
    load_chunk(sb, 1, 1, tid, m0, n0, Xhi, Xlo, Whi, Wlo);
    asm volatile("cp.async.wait_group 1;" ::: "memory");
    __syncthreads();

    float acc[4][8][4];
#pragma unroll
    for (int i = 0; i < 4; i++)
#pragma unroll
        for (int j = 0; j < 8; j++)
#pragma unroll
            for (int q = 0; q < 4; q++) acc[i][j][q] = 0.f;

#pragma unroll 1
    for (int kc = 0; kc < NCHUNK; ++kc) {
        const int s = kc % NSTAGE;
        if (kc + 2 < NCHUNK)
            load_chunk(sb, (kc + 2) % NSTAGE, kc + 2, tid, m0, n0, Xhi, Xlo, Whi, Wlo);

        const uint32_t st = sb + (uint32_t)s * STAGE_BYTES;
#pragma unroll
        for (int ks = 0; ks < 2; ks++) {
            const uint32_t ko = ks * 32;            // 16 elems * 2B
            uint32_t fxh[4][4], fxl[4][4];
#pragma unroll
            for (int mf = 0; mf < 4; mf++) {
                uint32_t ao = a_base + (uint32_t)(mf * 16 * ROWB) + ko;
                ldsm4(fxh[mf], st + OFF_AHI + ao);
                ldsm4(fxl[mf], st + OFF_ALO + ao);
            }
#pragma unroll
            for (int nfp = 0; nfp < 4; nfp++) {
                uint32_t wh[4], wl[4];
                uint32_t bo = b_base + (uint32_t)(nfp * 16 * ROWB) + ko;
                ldsm4(wh, st + OFF_BHI + bo);
                ldsm4(wl, st + OFF_BLO + bo);
#pragma unroll
                for (int mf = 0; mf < 4; mf++) {
                    mma16816(acc[mf][2 * nfp],     fxh[mf], wh);
                    mma16816(acc[mf][2 * nfp + 1], fxh[mf], wh + 2);
                }
#pragma unroll
                for (int mf = 0; mf < 4; mf++) {
                    mma16816(acc[mf][2 * nfp],     fxl[mf], wh);
                    mma16816(acc[mf][2 * nfp + 1], fxl[mf], wh + 2);
                }
#pragma unroll
                for (int mf = 0; mf < 4; mf++) {
                    mma16816(acc[mf][2 * nfp],     fxh[mf], wl);
                    mma16816(acc[mf][2 * nfp + 1], fxh[mf], wl + 2);
                }
            }
        }

        if (kc + 2 < NCHUNK)
            asm volatile("cp.async.wait_group 1;" ::: "memory");
        else
            asm volatile("cp.async.wait_group 0;" ::: "memory");
        __syncthreads();
    }

    // epilogue
#pragma unroll
    for (int mf = 0; mf < 4; mf++) {
#pragma unroll
        for (int nf = 0; nf < 8; nf++) {
            const float* c = acc[mf][nf];
            int row0 = m0 + wm * 64 + mf * 16 + (lane >> 2);
            int row1 = row0 + 8;
            int n = n0 + wn * 64 + nf * 8 + 2 * (lane & 3);
            float bn0 = bias[n], bn1 = bias[n + 1];
            size_t o0 = (size_t)row0 * DIMV + n;
            size_t o1 = (size_t)row1 * DIMV + n;
            if (mode == 0) {
                float v00 = fmaxf(c[0] + bn0, 0.f), v01 = fmaxf(c[1] + bn1, 0.f);
                float v10 = fmaxf(c[2] + bn0, 0.f), v11 = fmaxf(c[3] + bn1, 0.f);
                __nv_bfloat162 h2, l2;
                h2.x = __float2bfloat16(v00); l2.x = __float2bfloat16(v00 - __bfloat162float(h2.x));
                h2.y = __float2bfloat16(v01); l2.y = __float2bfloat16(v01 - __bfloat162float(h2.y));
                *(__nv_bfloat162*)(Ohi + o0) = h2;
                *(__nv_bfloat162*)(Olo + o0) = l2;
                h2.x = __float2bfloat16(v10); l2.x = __float2bfloat16(v10 - __bfloat162float(h2.x));
                h2.y = __float2bfloat16(v11); l2.y = __float2bfloat16(v11 - __bfloat162float(h2.y));
                *(__nv_bfloat162*)(Ohi + o1) = h2;
                *(__nv_bfloat162*)(Olo + o1) = l2;
            } else {
                float2 hv0 = *(const float2*)(hin + o0);
                float2 hv1 = *(const float2*)(hin + o1);
                float2 r0v; r0v.x = c[0] + bn0 + hv0.x; r0v.y = c[1] + bn1 + hv0.y;
                float2 r1v; r1v.x = c[2] + bn0 + hv1.x; r1v.y = c[3] + bn1 + hv1.y;
                *(float2*)(fout + o0) = r0v;
                *(float2*)(fout + o1) = r1v;
            }
        }
    }
}

// ---------------------------------------------------------------------------
// LayerNorm (validated in R3)
// ---------------------------------------------------------------------------
__global__ __launch_bounds__(256) void ln_kernel(
    const float* __restrict__ t, const float* __restrict__ g,
    const float* __restrict__ bb, float* __restrict__ hout,
    __nv_bfloat16* __restrict__ Ohi, __nv_bfloat16* __restrict__ Olo)
{
    int row = blockIdx.x;
    int tid = threadIdx.x;
    const float* tr = t + (size_t)row * DIMV;

    float v[4];
#pragma unroll
    for (int i = 0; i < 4; i++) v[i] = tr[tid + 256 * i];

    float s = v[0] + v[1] + v[2] + v[3];
#pragma unroll
    for (int o = 16; o > 0; o >>= 1) s += __shfl_xor_sync(0xffffffffu, s, o);

    __shared__ float red[8];
    int w = tid >> 5, ln = tid & 31;
    if (ln == 0) red[w] = s;
    __syncthreads();
    float tot = 0.f;
#pragma unroll
    for (int i = 0; i < 8; i++) tot += red[i];
    float mu = tot * (1.0f / 1024.0f);

    float sq = 0.f;
#pragma unroll
    for (int i = 0; i < 4; i++) { float d = v[i] - mu; sq += d * d; }
#pragma unroll
    for (int o = 16; o > 0; o >>= 1) sq += __shfl_xor_sync(0xffffffffu, sq, o);
    __syncthreads();
    if (ln == 0) red[w] = sq;
    __syncthreads();
    float vtot = 0.f;
#pragma unroll
    for (int i = 0; i < 8; i++) vtot += red[i];
    float rs = rsqrtf(vtot * (1.0f / 1024.0f) + 1e-5f);

#pragma unroll
    for (int i = 0; i < 4; i++) {
        int col = tid + 256 * i;
        float o = (v[i] - mu) * rs * g[col] + bb[col];
        size_t idx = (size_t)row * DIMV + col;
        hout[idx] = o;
        __nv_bfloat16 h = __float2bfloat16(o);
        Ohi[idx] = h;
        Olo[idx] = __float2bfloat16(o - __bfloat162float(h));
    }
}

// ---------------------------------------------------------------------------
// Host
// ---------------------------------------------------------------------------
extern "C" void kernel_launch(void* const* d_in, const int* in_sizes, int n_in,
                              void* d_out, int out_size)
{
    const float* x      = (const float*)d_in[0];
    const int*   qw     = (const int*)d_in[1];
    const float* scales = (const float*)d_in[2];
    const float* bias   = (const float*)d_in[3];
    const float* la     = (const float*)d_in[4];
    const float* lb     = (const float*)d_in[5];
    const float* lng    = (const float*)d_in[6];
    const float* lnb    = (const float*)d_in[7];
    float* out = (float*)d_out;

    void* p;
    cudaGetSymbolAddress(&p, g_Whi);  __nv_bfloat16* Whi  = (__nv_bfloat16*)p;
    cudaGetSymbolAddress(&p, g_Wlo);  __nv_bfloat16* Wlo  = (__nv_bfloat16*)p;
    cudaGetSymbolAddress(&p, g_ahi0); __nv_bfloat16* Ahi0 = (__nv_bfloat16*)p;
    cudaGetSymbolAddress(&p, g_alo0); __nv_bfloat16* Alo0 = (__nv_bfloat16*)p;
    cudaGetSymbolAddress(&p, g_ahi1); __nv_bfloat16* Ahi1 = (__nv_bfloat16*)p;
    cudaGetSymbolAddress(&p, g_alo1); __nv_bfloat16* Alo1 = (__nv_bfloat16*)p;
    cudaGetSymbolAddress(&p, g_ybuf); float* Ybuf = (float*)p;
    cudaGetSymbolAddress(&p, g_h);    float* Hbuf = (float*)p;

    __nv_bfloat16* ahi[2] = {Ahi0, Ahi1};
    __nv_bfloat16* alo[2] = {Alo0, Alo1};

    cudaFuncSetAttribute(gemm_kernel,
                         cudaFuncAttributeMaxDynamicSharedMemorySize, SMEM_TOTAL);

    prep_w_kernel<<<dim3(16, 16, NL), 256>>>(qw, scales, la, lb, Whi, Wlo);
    split_x_kernel<<<(BV * DIMV) / 256, 256>>>(x, ahi[0], alo[0]);

    for (int l = 0; l < NL; l++) {
        int ib = l & 1, ob = (l + 1) & 1;
        const __nv_bfloat16* wh = Whi + (size_t)l * DIMV * DIMV;
        const __nv_bfloat16* wl = Wlo + (size_t)l * DIMV * DIMV;
        const float* bl = bias + (size_t)l * DIMV;

        if (l % 3 != 2) {
            gemm_kernel<<<dim3(DIMV / TN, BV / TM), 256, SMEM_TOTAL>>>(
                ahi[ib], alo[ib], wh, wl, bl, 0, nullptr, nullptr,
                ahi[ob], alo[ob]);
        } else {
            const float* hin = (l == 2) ? x : Hbuf;
            float* fo = (l == NL - 1) ? out : Ybuf;
            gemm_kernel<<<dim3(DIMV / TN, BV / TM), 256, SMEM_TOTAL>>>(
                ahi[ib], alo[ib], wh, wl, bl, 1, hin, fo, nullptr, nullptr);
            if (l != NL - 1) {
                int blk = l / 3;
                ln_kernel<<<BV, 256>>>(Ybuf, lng + (size_t)blk * DIMV,
                                       lnb + (size_t)blk * DIMV, Hbuf,
                                       ahi[ob], alo[ob]);
            }
        }
    }
}

// round 6
// speedup vs baseline: 1.1219x; 1.0065x over previous
#include <cuda_runtime.h>
#include <cuda_bf16.h>
#include <cstdint>
#include <cstddef>

// ---------------------------------------------------------------------------
// QLoRABigNet, mma.sync path (tcgen05 unavailable at compute_103 PTX target).
// 18 layers of y = x @ W_eff^T + bias (+relu / +residual / LN).
// W_eff = dequant_int4 + lora_b@lora_a precomputed; split-bf16 3-MMA numerics.
// R6: 512 threads (16 warps, warp tile 64x32) + term-major MMA ordering.
// ---------------------------------------------------------------------------

#define NL    18
#define DIMV  1024
#define BV    32768
#define NGRP  64

#define TM 256
#define TN 128
#define KC 32
#define NCHUNK (DIMV / KC)       // 32
#define NTHR 512

#define ROWB 80
#define OFF_AHI 0
#define OFF_ALO 20480            // 256*80
#define OFF_BHI 40960
#define OFF_BLO 51200
#define STAGE_BYTES 61440
#define NSTAGE 3
#define SMEM_TOTAL (NSTAGE * STAGE_BYTES)   // 184320

// ---- scratch (device globals: allocation-free contract) --------------------
__device__ __nv_bfloat16 g_Whi[(size_t)NL * DIMV * DIMV];
__device__ __nv_bfloat16 g_Wlo[(size_t)NL * DIMV * DIMV];
__device__ __nv_bfloat16 g_ahi0[(size_t)BV * DIMV];
__device__ __nv_bfloat16 g_alo0[(size_t)BV * DIMV];
__device__ __nv_bfloat16 g_ahi1[(size_t)BV * DIMV];
__device__ __nv_bfloat16 g_alo1[(size_t)BV * DIMV];
__device__ float         g_ybuf[(size_t)BV * DIMV];
__device__ float         g_h[(size_t)BV * DIMV];

// ---------------------------------------------------------------------------
// PTX helpers
// ---------------------------------------------------------------------------
__device__ __forceinline__ void ldsm4(uint32_t* r, uint32_t a) {
    asm volatile("ldmatrix.sync.aligned.m8n8.x4.shared.b16 {%0,%1,%2,%3}, [%4];\n"
                 : "=r"(r[0]), "=r"(r[1]), "=r"(r[2]), "=r"(r[3]) : "r"(a));
}
__device__ __forceinline__ void mma16816(float* c, const uint32_t* a, const uint32_t* b) {
    asm volatile(
        "mma.sync.aligned.m16n8k16.row.col.f32.bf16.bf16.f32 "
        "{%0,%1,%2,%3}, {%4,%5,%6,%7}, {%8,%9}, {%0,%1,%2,%3};\n"
        : "+f"(c[0]), "+f"(c[1]), "+f"(c[2]), "+f"(c[3])
        : "r"(a[0]), "r"(a[1]), "r"(a[2]), "r"(a[3]), "r"(b[0]), "r"(b[1]));
}
__device__ __forceinline__ void cpa16(uint32_t dst, const void* src) {
    asm volatile("cp.async.cg.shared.global [%0], [%1], 16;" :: "r"(dst), "l"(src));
}
__device__ __forceinline__ void cp_commit() {
    asm volatile("cp.async.commit_group;" ::: "memory");
}

// ---------------------------------------------------------------------------
// Prepass: W_eff = qw*scale + B@A, split bf16 hi/lo. (validated R3/R5)
// ---------------------------------------------------------------------------
__global__ __launch_bounds__(256) void prep_w_kernel(
    const int* __restrict__ qw, const float* __restrict__ sc,
    const float* __restrict__ la, const float* __restrict__ lb,
    __nv_bfloat16* __restrict__ Whi, __nv_bfloat16* __restrict__ Wlo)
{
    int l  = blockIdx.z;
    int o0 = blockIdx.y * 64;
    int k0 = blockIdx.x * 64;
    int tid = threadIdx.x;

    __shared__ float sLb[64][32];
    __shared__ float sLa[32][64];

    const float* lbp = lb + (size_t)l * DIMV * 32;
    const float* lap = la + (size_t)l * 32 * DIMV;

#pragma unroll
    for (int i = 0; i < 8; i++) {
        int off = tid + i * 256;
        int o = off >> 5, r = off & 31;
        sLb[o][r] = lbp[(size_t)(o0 + o) * 32 + r];
        int r2 = off >> 6, k = off & 63;
        sLa[r2][k] = lap[(size_t)r2 * DIMV + k0 + k];
    }
    __syncthreads();

    int to = tid >> 4, tk = tid & 15;
    float m[4][4];
#pragma unroll
    for (int i = 0; i < 4; i++)
#pragma unroll
        for (int j = 0; j < 4; j++) m[i][j] = 0.f;

#pragma unroll 8
    for (int r = 0; r < 32; r++) {
        float av[4], bv[4];
#pragma unroll
        for (int j = 0; j < 4; j++) av[j] = sLa[r][tk * 4 + j];
#pragma unroll
        for (int i = 0; i < 4; i++) bv[i] = sLb[to * 4 + i][r];
#pragma unroll
        for (int i = 0; i < 4; i++)
#pragma unroll
            for (int j = 0; j < 4; j++) m[i][j] += bv[i] * av[j];
    }

#pragma unroll
    for (int i = 0; i < 4; i++) {
        int o = o0 + to * 4 + i;
        const int*   qrow = qw + ((size_t)l * DIMV + o) * DIMV + k0;
        const float* srow = sc + ((size_t)l * DIMV + o) * NGRP;
#pragma unroll
        for (int j = 0; j < 4; j++) {
            int k = k0 + tk * 4 + j;
            float wv = (float)qrow[tk * 4 + j] * srow[k >> 4] + m[i][j];
            size_t idx = ((size_t)l * DIMV + o) * DIMV + k;
            __nv_bfloat16 h = __float2bfloat16(wv);
            Whi[idx] = h;
            Wlo[idx] = __float2bfloat16(wv - __bfloat162float(h));
        }
    }
}

__global__ __launch_bounds__(256) void split_x_kernel(
    const float* __restrict__ x, __nv_bfloat16* __restrict__ hi,
    __nv_bfloat16* __restrict__ lo)
{
    size_t i = (size_t)blockIdx.x * 256 + threadIdx.x;
    float v = x[i];
    __nv_bfloat16 h = __float2bfloat16(v);
    hi[i] = h;
    lo[i] = __float2bfloat16(v - __bfloat162float(h));
}

// ---------------------------------------------------------------------------
// GEMM: C[BV,DIMV] = X @ W^T. grid (8, 128), 512 threads, 16 warps (4x4),
// warp tile 64x32. 3-stage cp.async, K-chunk 32.
// mode 0: out = relu(acc+bias) -> bf16 hi/lo ; mode 1: out = acc+bias+hin fp32
// ---------------------------------------------------------------------------
__device__ __forceinline__ void load_chunk(
    uint32_t sb, int s, int kc, int tid, int m0, int n0,
    const __nv_bfloat16* __restrict__ Xhi, const __nv_bfloat16* __restrict__ Xlo,
    const __nv_bfloat16* __restrict__ Whi, const __nv_bfloat16* __restrict__ Wlo)
{
    const uint32_t st = sb + (uint32_t)s * STAGE_BYTES;
    const int kbase = kc * KC;
    // A: 256 rows x 32 elems; 1024 16B-segments -> 2 iters of 512 threads
#pragma unroll
    for (int i = 0; i < 2; i++) {
        int idx = i * NTHR + tid;
        int row = idx >> 2, seg = idx & 3;
        uint32_t off = (uint32_t)(row * ROWB + seg * 16);
        const size_t gsrc = (size_t)(m0 + row) * DIMV + kbase + seg * 8;
        cpa16(st + OFF_AHI + off, Xhi + gsrc);
        cpa16(st + OFF_ALO + off, Xlo + gsrc);
    }
    // B: 128 rows x 32 elems; 512 16B-segments -> 1 iter
    {
        int row = tid >> 2, seg = tid & 3;
        uint32_t off = (uint32_t)(row * ROWB + seg * 16);
        const size_t gsrc = (size_t)(n0 + row) * DIMV + kbase + seg * 8;
        cpa16(st + OFF_BHI + off, Whi + gsrc);
        cpa16(st + OFF_BLO + off, Wlo + gsrc);
    }
    cp_commit();
}

__global__ __launch_bounds__(NTHR, 1) void gemm_kernel(
    const __nv_bfloat16* __restrict__ Xhi, const __nv_bfloat16* __restrict__ Xlo,
    const __nv_bfloat16* __restrict__ Whi, const __nv_bfloat16* __restrict__ Wlo,
    const float* __restrict__ bias, int mode,
    const float* __restrict__ hin, float* __restrict__ fout,
    __nv_bfloat16* __restrict__ Ohi, __nv_bfloat16* __restrict__ Olo)
{
    extern __shared__ __align__(128) char smem[];
    const uint32_t sb = (uint32_t)__cvta_generic_to_shared(smem);

    const int tid = threadIdx.x, warp = tid >> 5, lane = tid & 31;
    const int wm = warp >> 2, wn = warp & 3;         // 4 x 4 warp grid, 64x32 tile
    const int m0 = blockIdx.y * TM, n0 = blockIdx.x * TN;

    // ldmatrix per-lane addressing (bytes, relative to stage base)
    const int mi = lane >> 3, rr = lane & 7;
    const uint32_t a_base = (uint32_t)((wm * 64 + (mi & 1) * 8 + rr) * ROWB
                                       + ((mi >> 1) * 8) * 2);
    const uint32_t b_base = (uint32_t)((wn * 32 + ((lane >> 4) << 3) + (lane & 7)) * ROWB
                                       + (((lane >> 3) & 1) * 8) * 2);

    // prologue: chunks 0,1
    load_chunk(sb, 0, 0, tid, m0, n0, Xhi, Xlo, Whi, Wlo);
    load_chunk(sb, 1, 1, tid, m0, n0, Xhi, Xlo, Whi, Wlo);
    asm volatile("cp.async.wait_group 1;" ::: "memory");
    __syncthreads();

    float acc[4][4][4];
#pragma unroll
    for (int i = 0; i < 4; i++)
#pragma unroll
        for (int j = 0; j < 4; j++)
#pragma unroll
            for (int q = 0; q < 4; q++) acc[i][j][q] = 0.f;

#pragma unroll 1
    for (int kc = 0; kc < NCHUNK; ++kc) {
        const int s = kc % NSTAGE;
        if (kc + 2 < NCHUNK)
            load_chunk(sb, (kc + 2) % NSTAGE, kc + 2, tid, m0, n0, Xhi, Xlo, Whi, Wlo);

        const uint32_t st = sb + (uint32_t)s * STAGE_BYTES;
#pragma unroll
        for (int ks = 0; ks < 2; ks++) {
            const uint32_t ko = ks * 32;            // 16 elems * 2B

            // load ALL fragments for this k16 first (frees MMA scheduling)
            uint32_t wh[8], wl[8];
#pragma unroll
            for (int nfp = 0; nfp < 2; nfp++) {
                uint32_t bo = b_base + (uint32_t)(nfp * 16 * ROWB) + ko;
                ldsm4(wh + 4 * nfp, st + OFF_BHI + bo);
                ldsm4(wl + 4 * nfp, st + OFF_BLO + bo);
            }
            uint32_t fxh[4][4], fxl[4][4];
#pragma unroll
            for (int mf = 0; mf < 4; mf++) {
                uint32_t ao = a_base + (uint32_t)(mf * 16 * ROWB) + ko;
                ldsm4(fxh[mf], st + OFF_AHI + ao);
                ldsm4(fxl[mf], st + OFF_ALO + ao);
            }

            // term-major: 16 independent HMMAs per pass (acc reuse distance 16)
#pragma unroll
            for (int mf = 0; mf < 4; mf++)
#pragma unroll
                for (int nf = 0; nf < 4; nf++)
                    mma16816(acc[mf][nf], fxh[mf], wh + 2 * nf);
#pragma unroll
            for (int mf = 0; mf < 4; mf++)
#pragma unroll
                for (int nf = 0; nf < 4; nf++)
                    mma16816(acc[mf][nf], fxl[mf], wh + 2 * nf);
#pragma unroll
            for (int mf = 0; mf < 4; mf++)
#pragma unroll
                for (int nf = 0; nf < 4; nf++)
                    mma16816(acc[mf][nf], fxh[mf], wl + 2 * nf);
        }

        if (kc + 2 < NCHUNK)
            asm volatile("cp.async.wait_group 1;" ::: "memory");
        else
            asm volatile("cp.async.wait_group 0;" ::: "memory");
        __syncthreads();
    }

    // epilogue
#pragma unroll
    for (int mf = 0; mf < 4; mf++) {
#pragma unroll
        for (int nf = 0; nf < 4; nf++) {
            const float* c = acc[mf][nf];
            int row0 = m0 + wm * 64 + mf * 16 + (lane >> 2);
            int row1 = row0 + 8;
            int n = n0 + wn * 32 + nf * 8 + 2 * (lane & 3);
            float bn0 = bias[n], bn1 = bias[n + 1];
            size_t o0 = (size_t)row0 * DIMV + n;
            size_t o1 = (size_t)row1 * DIMV + n;
            if (mode == 0) {
                float v00 = fmaxf(c[0] + bn0, 0.f), v01 = fmaxf(c[1] + bn1, 0.f);
                float v10 = fmaxf(c[2] + bn0, 0.f), v11 = fmaxf(c[3] + bn1, 0.f);
                __nv_bfloat162 h2, l2;
                h2.x = __float2bfloat16(v00); l2.x = __float2bfloat16(v00 - __bfloat162float(h2.x));
                h2.y = __float2bfloat16(v01); l2.y = __float2bfloat16(v01 - __bfloat162float(h2.y));
                *(__nv_bfloat162*)(Ohi + o0) = h2;
                *(__nv_bfloat162*)(Olo + o0) = l2;
                h2.x = __float2bfloat16(v10); l2.x = __float2bfloat16(v10 - __bfloat162float(h2.x));
                h2.y = __float2bfloat16(v11); l2.y = __float2bfloat16(v11 - __bfloat162float(h2.y));
                *(__nv_bfloat162*)(Ohi + o1) = h2;
                *(__nv_bfloat162*)(Olo + o1) = l2;
            } else {
                float2 hv0 = *(const float2*)(hin + o0);
                float2 hv1 = *(const float2*)(hin + o1);
                float2 r0v; r0v.x = c[0] + bn0 + hv0.x; r0v.y = c[1] + bn1 + hv0.y;
                float2 r1v; r1v.x = c[2] + bn0 + hv1.x; r1v.y = c[3] + bn1 + hv1.y;
                *(float2*)(fout + o0) = r0v;
                *(float2*)(fout + o1) = r1v;
            }
        }
    }
}

// ---------------------------------------------------------------------------
// LayerNorm (validated R3/R5)
// ---------------------------------------------------------------------------
__global__ __launch_bounds__(256) void ln_kernel(
    const float* __restrict__ t, const float* __restrict__ g,
    const float* __restrict__ bb, float* __restrict__ hout,
    __nv_bfloat16* __restrict__ Ohi, __nv_bfloat16* __restrict__ Olo)
{
    int row = blockIdx.x;
    int tid = threadIdx.x;
    const float* tr = t + (size_t)row * DIMV;

    float v[4];
#pragma unroll
    for (int i = 0; i < 4; i++) v[i] = tr[tid + 256 * i];

    float s = v[0] + v[1] + v[2] + v[3];
#pragma unroll
    for (int o = 16; o > 0; o >>= 1) s += __shfl_xor_sync(0xffffffffu, s, o);

    __shared__ float red[8];
    int w = tid >> 5, ln = tid & 31;
    if (ln == 0) red[w] = s;
    __syncthreads();
    float tot = 0.f;
#pragma unroll
    for (int i = 0; i < 8; i++) tot += red[i];
    float mu = tot * (1.0f / 1024.0f);

    float sq = 0.f;
#pragma unroll
    for (int i = 0; i < 4; i++) { float d = v[i] - mu; sq += d * d; }
#pragma unroll
    for (int o = 16; o > 0; o >>= 1) sq += __shfl_xor_sync(0xffffffffu, sq, o);
    __syncthreads();
    if (ln == 0) red[w] = sq;
    __syncthreads();
    float vtot = 0.f;
#pragma unroll
    for (int i = 0; i < 8; i++) vtot += red[i];
    float rs = rsqrtf(vtot * (1.0f / 1024.0f) + 1e-5f);

#pragma unroll
    for (int i = 0; i < 4; i++) {
        int col = tid + 256 * i;
        float o = (v[i] - mu) * rs * g[col] + bb[col];
        size_t idx = (size_t)row * DIMV + col;
        hout[idx] = o;
        __nv_bfloat16 h = __float2bfloat16(o);
        Ohi[idx] = h;
        Olo[idx] = __float2bfloat16(o - __bfloat162float(h));
    }
}

// ---------------------------------------------------------------------------
// Host
// ---------------------------------------------------------------------------
extern "C" void kernel_launch(void* const* d_in, const int* in_sizes, int n_in,
                              void* d_out, int out_size)
{
    const float* x      = (const float*)d_in[0];
    const int*   qw     = (const int*)d_in[1];
    const float* scales = (const float*)d_in[2];
    const float* bias   = (const float*)d_in[3];
    const float* la     = (const float*)d_in[4];
    const float* lb     = (const float*)d_in[5];
    const float* lng    = (const float*)d_in[6];
    const float* lnb    = (const float*)d_in[7];
    float* out = (float*)d_out;

    void* p;
    cudaGetSymbolAddress(&p, g_Whi);  __nv_bfloat16* Whi  = (__nv_bfloat16*)p;
    cudaGetSymbolAddress(&p, g_Wlo);  __nv_bfloat16* Wlo  = (__nv_bfloat16*)p;
    cudaGetSymbolAddress(&p, g_ahi0); __nv_bfloat16* Ahi0 = (__nv_bfloat16*)p;
    cudaGetSymbolAddress(&p, g_alo0); __nv_bfloat16* Alo0 = (__nv_bfloat16*)p;
    cudaGetSymbolAddress(&p, g_ahi1); __nv_bfloat16* Ahi1 = (__nv_bfloat16*)p;
    cudaGetSymbolAddress(&p, g_alo1); __nv_bfloat16* Alo1 = (__nv_bfloat16*)p;
    cudaGetSymbolAddress(&p, g_ybuf); float* Ybuf = (float*)p;
    cudaGetSymbolAddress(&p, g_h);    float* Hbuf = (float*)p;

    __nv_bfloat16* ahi[2] = {Ahi0, Ahi1};
    __nv_bfloat16* alo[2] = {Alo0, Alo1};

    cudaFuncSetAttribute(gemm_kernel,
                         cudaFuncAttributeMaxDynamicSharedMemorySize, SMEM_TOTAL);

    prep_w_kernel<<<dim3(16, 16, NL), 256>>>(qw, scales, la, lb, Whi, Wlo);
    split_x_kernel<<<(BV * DIMV) / 256, 256>>>(x, ahi[0], alo[0]);

    for (int l = 0; l < NL; l++) {
        int ib = l & 1, ob = (l + 1) & 1;
        const __nv_bfloat16* wh = Whi + (size_t)l * DIMV * DIMV;
        const __nv_bfloat16* wl = Wlo + (size_t)l * DIMV * DIMV;
        const float* bl = bias + (size_t)l * DIMV;

        if (l % 3 != 2) {
            gemm_kernel<<<dim3(DIMV / TN, BV / TM), NTHR, SMEM_TOTAL>>>(
                ahi[ib], alo[ib], wh, wl, bl, 0, nullptr, nullptr,
                ahi[ob], alo[ob]);
        } else {
            const float* hin = (l == 2) ? x : Hbuf;
            float* fo = (l == NL - 1) ? out : Ybuf;
            gemm_kernel<<<dim3(DIMV / TN, BV / TM), NTHR, SMEM_TOTAL>>>(
                ahi[ib], alo[ib], wh, wl, bl, 1, hin, fo, nullptr, nullptr);
            if (l != NL - 1) {
                int blk = l / 3;
                ln_kernel<<<BV, 256>>>(Ybuf, lng + (size_t)blk * DIMV,
                                       lnb + (size_t)blk * DIMV, Hbuf,
                                       ahi[ob], alo[ob]);
            }
        }
    }
}

// round 7
// speedup vs baseline: 1.2365x; 1.1021x over previous
#include <cuda_runtime.h>
#include <cuda_bf16.h>
#include <cstdint>
#include <cstddef>

// ---------------------------------------------------------------------------
// QLoRABigNet, mma.sync path (tcgen05 unavailable at compute_103 PTX target).
// 18 layers of y = x @ W_eff^T + bias (+relu / +residual / LN).
// W_eff = dequant_int4 + lora_b@lora_a precomputed; split-bf16 3-MMA numerics.
// R7: CTA 128x128, 256 thr, 2-stage cp.async, 2 CTAs/SM so one CTA's
//     barrier/wait bubble is covered by the other CTA's MMA stream.
// ---------------------------------------------------------------------------

#define NL    18
#define DIMV  1024
#define BV    32768
#define NGRP  64

#define TM 128
#define TN 128
#define KC 32
#define NCHUNK (DIMV / KC)       // 32
#define NTHR 256

#define ROWB 80
#define OFF_AHI 0
#define OFF_ALO 10240            // 128*80
#define OFF_BHI 20480
#define OFF_BLO 30720
#define STAGE_BYTES 40960
#define NSTAGE 2
#define SMEM_TOTAL (NSTAGE * STAGE_BYTES)   // 81920 -> 2 CTAs/SM

// ---- scratch (device globals: allocation-free contract) --------------------
__device__ __nv_bfloat16 g_Whi[(size_t)NL * DIMV * DIMV];
__device__ __nv_bfloat16 g_Wlo[(size_t)NL * DIMV * DIMV];
__device__ __nv_bfloat16 g_ahi0[(size_t)BV * DIMV];
__device__ __nv_bfloat16 g_alo0[(size_t)BV * DIMV];
__device__ __nv_bfloat16 g_ahi1[(size_t)BV * DIMV];
__device__ __nv_bfloat16 g_alo1[(size_t)BV * DIMV];
__device__ float         g_ybuf[(size_t)BV * DIMV];
__device__ float         g_h[(size_t)BV * DIMV];

// ---------------------------------------------------------------------------
// PTX helpers
// ---------------------------------------------------------------------------
__device__ __forceinline__ void ldsm4(uint32_t* r, uint32_t a) {
    asm volatile("ldmatrix.sync.aligned.m8n8.x4.shared.b16 {%0,%1,%2,%3}, [%4];\n"
                 : "=r"(r[0]), "=r"(r[1]), "=r"(r[2]), "=r"(r[3]) : "r"(a));
}
__device__ __forceinline__ void mma16816(float* c, const uint32_t* a, const uint32_t* b) {
    asm volatile(
        "mma.sync.aligned.m16n8k16.row.col.f32.bf16.bf16.f32 "
        "{%0,%1,%2,%3}, {%4,%5,%6,%7}, {%8,%9}, {%0,%1,%2,%3};\n"
        : "+f"(c[0]), "+f"(c[1]), "+f"(c[2]), "+f"(c[3])
        : "r"(a[0]), "r"(a[1]), "r"(a[2]), "r"(a[3]), "r"(b[0]), "r"(b[1]));
}
__device__ __forceinline__ void cpa16(uint32_t dst, const void* src) {
    asm volatile("cp.async.cg.shared.global [%0], [%1], 16;" :: "r"(dst), "l"(src));
}
__device__ __forceinline__ void cp_commit() {
    asm volatile("cp.async.commit_group;" ::: "memory");
}

// ---------------------------------------------------------------------------
// Prepass: W_eff = qw*scale + B@A, split bf16 hi/lo. (validated R3/R5/R6)
// ---------------------------------------------------------------------------
__global__ __launch_bounds__(256) void prep_w_kernel(
    const int* __restrict__ qw, const float* __restrict__ sc,
    const float* __restrict__ la, const float* __restrict__ lb,
    __nv_bfloat16* __restrict__ Whi, __nv_bfloat16* __restrict__ Wlo)
{
    int l  = blockIdx.z;
    int o0 = blockIdx.y * 64;
    int k0 = blockIdx.x * 64;
    int tid = threadIdx.x;

    __shared__ float sLb[64][32];
    __shared__ float sLa[32][64];

    const float* lbp = lb + (size_t)l * DIMV * 32;
    const float* lap = la + (size_t)l * 32 * DIMV;

#pragma unroll
    for (int i = 0; i < 8; i++) {
        int off = tid + i * 256;
        int o = off >> 5, r = off & 31;
        sLb[o][r] = lbp[(size_t)(o0 + o) * 32 + r];
        int r2 = off >> 6, k = off & 63;
        sLa[r2][k] = lap[(size_t)r2 * DIMV + k0 + k];
    }
    __syncthreads();

    int to = tid >> 4, tk = tid & 15;
    float m[4][4];
#pragma unroll
    for (int i = 0; i < 4; i++)
#pragma unroll
        for (int j = 0; j < 4; j++) m[i][j] = 0.f;

#pragma unroll 8
    for (int r = 0; r < 32; r++) {
        float av[4], bv[4];
#pragma unroll
        for (int j = 0; j < 4; j++) av[j] = sLa[r][tk * 4 + j];
#pragma unroll
        for (int i = 0; i < 4; i++) bv[i] = sLb[to * 4 + i][r];
#pragma unroll
        for (int i = 0; i < 4; i++)
#pragma unroll
            for (int j = 0; j < 4; j++) m[i][j] += bv[i] * av[j];
    }

#pragma unroll
    for (int i = 0; i < 4; i++) {
        int o = o0 + to * 4 + i;
        const int*   qrow = qw + ((size_t)l * DIMV + o) * DIMV + k0;
        const float* srow = sc + ((size_t)l * DIMV + o) * NGRP;
#pragma unroll
        for (int j = 0; j < 4; j++) {
            int k = k0 + tk * 4 + j;
            float wv = (float)qrow[tk * 4 + j] * srow[k >> 4] + m[i][j];
            size_t idx = ((size_t)l * DIMV + o) * DIMV + k;
            __nv_bfloat16 h = __float2bfloat16(wv);
            Whi[idx] = h;
            Wlo[idx] = __float2bfloat16(wv - __bfloat162float(h));
        }
    }
}

__global__ __launch_bounds__(256) void split_x_kernel(
    const float* __restrict__ x, __nv_bfloat16* __restrict__ hi,
    __nv_bfloat16* __restrict__ lo)
{
    size_t i = (size_t)blockIdx.x * 256 + threadIdx.x;
    float v = x[i];
    __nv_bfloat16 h = __float2bfloat16(v);
    hi[i] = h;
    lo[i] = __float2bfloat16(v - __bfloat162float(h));
}

// ---------------------------------------------------------------------------
// GEMM: C[BV,DIMV] = X @ W^T. grid (8, 256), 256 threads, 8 warps (2x4),
// warp tile 64x32. 2-stage cp.async, K-chunk 32, 2 CTAs/SM.
// mode 0: out = relu(acc+bias) -> bf16 hi/lo ; mode 1: out = acc+bias+hin fp32
// ---------------------------------------------------------------------------
__device__ __forceinline__ void load_chunk(
    uint32_t sb, int s, int kc, int tid, int m0, int n0,
    const __nv_bfloat16* __restrict__ Xhi, const __nv_bfloat16* __restrict__ Xlo,
    const __nv_bfloat16* __restrict__ Whi, const __nv_bfloat16* __restrict__ Wlo)
{
    const uint32_t st = sb + (uint32_t)s * STAGE_BYTES;
    const int kbase = kc * KC;
    // A: 128 rows x 32 elems; 512 16B-segments -> 2 iters of 256 threads
#pragma unroll
    for (int i = 0; i < 2; i++) {
        int idx = i * NTHR + tid;
        int row = idx >> 2, seg = idx & 3;
        uint32_t off = (uint32_t)(row * ROWB + seg * 16);
        const size_t gsrc = (size_t)(m0 + row) * DIMV + kbase + seg * 8;
        cpa16(st + OFF_AHI + off, Xhi + gsrc);
        cpa16(st + OFF_ALO + off, Xlo + gsrc);
    }
    // B: 128 rows x 32 elems; 512 16B-segments -> 2 iters
#pragma unroll
    for (int i = 0; i < 2; i++) {
        int idx = i * NTHR + tid;
        int row = idx >> 2, seg = idx & 3;
        uint32_t off = (uint32_t)(row * ROWB + seg * 16);
        const size_t gsrc = (size_t)(n0 + row) * DIMV + kbase + seg * 8;
        cpa16(st + OFF_BHI + off, Whi + gsrc);
        cpa16(st + OFF_BLO + off, Wlo + gsrc);
    }
    cp_commit();
}

__global__ __launch_bounds__(NTHR, 2) void gemm_kernel(
    const __nv_bfloat16* __restrict__ Xhi, const __nv_bfloat16* __restrict__ Xlo,
    const __nv_bfloat16* __restrict__ Whi, const __nv_bfloat16* __restrict__ Wlo,
    const float* __restrict__ bias, int mode,
    const float* __restrict__ hin, float* __restrict__ fout,
    __nv_bfloat16* __restrict__ Ohi, __nv_bfloat16* __restrict__ Olo)
{
    extern __shared__ __align__(128) char smem[];
    const uint32_t sb = (uint32_t)__cvta_generic_to_shared(smem);

    const int tid = threadIdx.x, warp = tid >> 5, lane = tid & 31;
    const int wm = warp >> 2, wn = warp & 3;         // 2 x 4 warp grid, 64x32 tile
    const int m0 = blockIdx.y * TM, n0 = blockIdx.x * TN;

    // ldmatrix per-lane addressing (bytes, relative to stage base)
    const int mi = lane >> 3, rr = lane & 7;
    const uint32_t a_base = (uint32_t)((wm * 64 + (mi & 1) * 8 + rr) * ROWB
                                       + ((mi >> 1) * 8) * 2);
    const uint32_t b_base = (uint32_t)((wn * 32 + ((lane >> 4) << 3) + (lane & 7)) * ROWB
                                       + (((lane >> 3) & 1) * 8) * 2);

    // prologue: chunks 0 -> buf0, 1 -> buf1
    load_chunk(sb, 0, 0, tid, m0, n0, Xhi, Xlo, Whi, Wlo);
    load_chunk(sb, 1, 1, tid, m0, n0, Xhi, Xlo, Whi, Wlo);
    asm volatile("cp.async.wait_group 1;" ::: "memory");
    __syncthreads();

    float acc[4][4][4];
#pragma unroll
    for (int i = 0; i < 4; i++)
#pragma unroll
        for (int j = 0; j < 4; j++)
#pragma unroll
            for (int q = 0; q < 4; q++) acc[i][j][q] = 0.f;

#pragma unroll 1
    for (int kc = 0; kc < NCHUNK; ++kc) {
        const uint32_t st = sb + (uint32_t)(kc & 1) * STAGE_BYTES;
#pragma unroll
        for (int ks = 0; ks < 2; ks++) {
            const uint32_t ko = ks * 32;            // 16 elems * 2B

            // load ALL fragments for this k16 first
            uint32_t wh[8], wl[8];
#pragma unroll
            for (int nfp = 0; nfp < 2; nfp++) {
                uint32_t bo = b_base + (uint32_t)(nfp * 16 * ROWB) + ko;
                ldsm4(wh + 4 * nfp, st + OFF_BHI + bo);
                ldsm4(wl + 4 * nfp, st + OFF_BLO + bo);
            }
            uint32_t fxh[4][4], fxl[4][4];
#pragma unroll
            for (int mf = 0; mf < 4; mf++) {
                uint32_t ao = a_base + (uint32_t)(mf * 16 * ROWB) + ko;
                ldsm4(fxh[mf], st + OFF_AHI + ao);
                ldsm4(fxl[mf], st + OFF_ALO + ao);
            }

            // term-major: 16 independent HMMAs per pass
#pragma unroll
            for (int mf = 0; mf < 4; mf++)
#pragma unroll
                for (int nf = 0; nf < 4; nf++)
                    mma16816(acc[mf][nf], fxh[mf], wh + 2 * nf);
#pragma unroll
            for (int mf = 0; mf < 4; mf++)
#pragma unroll
                for (int nf = 0; nf < 4; nf++)
                    mma16816(acc[mf][nf], fxl[mf], wh + 2 * nf);
#pragma unroll
            for (int mf = 0; mf < 4; mf++)
#pragma unroll
                for (int nf = 0; nf < 4; nf++)
                    mma16816(acc[mf][nf], fxh[mf], wl + 2 * nf);
        }

        // chunk kc+1 (only outstanding group) must be resident for next iter
        asm volatile("cp.async.wait_group 0;" ::: "memory");
        __syncthreads();
        // refill the buffer we just consumed with chunk kc+2
        if (kc + 2 < NCHUNK)
            load_chunk(sb, kc & 1, kc + 2, tid, m0, n0, Xhi, Xlo, Whi, Wlo);
    }

    // epilogue
#pragma unroll
    for (int mf = 0; mf < 4; mf++) {
#pragma unroll
        for (int nf = 0; nf < 4; nf++) {
            const float* c = acc[mf][nf];
            int row0 = m0 + wm * 64 + mf * 16 + (lane >> 2);
            int row1 = row0 + 8;
            int n = n0 + wn * 32 + nf * 8 + 2 * (lane & 3);
            float bn0 = bias[n], bn1 = bias[n + 1];
            size_t o0 = (size_t)row0 * DIMV + n;
            size_t o1 = (size_t)row1 * DIMV + n;
            if (mode == 0) {
                float v00 = fmaxf(c[0] + bn0, 0.f), v01 = fmaxf(c[1] + bn1, 0.f);
                float v10 = fmaxf(c[2] + bn0, 0.f), v11 = fmaxf(c[3] + bn1, 0.f);
                __nv_bfloat162 h2, l2;
                h2.x = __float2bfloat16(v00); l2.x = __float2bfloat16(v00 - __bfloat162float(h2.x));
                h2.y = __float2bfloat16(v01); l2.y = __float2bfloat16(v01 - __bfloat162float(h2.y));
                *(__nv_bfloat162*)(Ohi + o0) = h2;
                *(__nv_bfloat162*)(Olo + o0) = l2;
                h2.x = __float2bfloat16(v10); l2.x = __float2bfloat16(v10 - __bfloat162float(h2.x));
                h2.y = __float2bfloat16(v11); l2.y = __float2bfloat16(v11 - __bfloat162float(h2.y));
                *(__nv_bfloat162*)(Ohi + o1) = h2;
                *(__nv_bfloat162*)(Olo + o1) = l2;
            } else {
                float2 hv0 = *(const float2*)(hin + o0);
                float2 hv1 = *(const float2*)(hin + o1);
                float2 r0v; r0v.x = c[0] + bn0 + hv0.x; r0v.y = c[1] + bn1 + hv0.y;
                float2 r1v; r1v.x = c[2] + bn0 + hv1.x; r1v.y = c[3] + bn1 + hv1.y;
                *(float2*)(fout + o0) = r0v;
                *(float2*)(fout + o1) = r1v;
            }
        }
    }
}

// ---------------------------------------------------------------------------
// LayerNorm (validated R3/R5/R6)
// ---------------------------------------------------------------------------
__global__ __launch_bounds__(256) void ln_kernel(
    const float* __restrict__ t, const float* __restrict__ g,
    const float* __restrict__ bb, float* __restrict__ hout,
    __nv_bfloat16* __restrict__ Ohi, __nv_bfloat16* __restrict__ Olo)
{
    int row = blockIdx.x;
    int tid = threadIdx.x;
    const float* tr = t + (size_t)row * DIMV;

    float v[4];
#pragma unroll
    for (int i = 0; i < 4; i++) v[i] = tr[tid + 256 * i];

    float s = v[0] + v[1] + v[2] + v[3];
#pragma unroll
    for (int o = 16; o > 0; o >>= 1) s += __shfl_xor_sync(0xffffffffu, s, o);

    __shared__ float red[8];
    int w = tid >> 5, ln = tid & 31;
    if (ln == 0) red[w] = s;
    __syncthreads();
    float tot = 0.f;
#pragma unroll
    for (int i = 0; i < 8; i++) tot += red[i];
    float mu = tot * (1.0f / 1024.0f);

    float sq = 0.f;
#pragma unroll
    for (int i = 0; i < 4; i++) { float d = v[i] - mu; sq += d * d; }
#pragma unroll
    for (int o = 16; o > 0; o >>= 1) sq += __shfl_xor_sync(0xffffffffu, sq, o);
    __syncthreads();
    if (ln == 0) red[w] = sq;
    __syncthreads();
    float vtot = 0.f;
#pragma unroll
    for (int i = 0; i < 8; i++) vtot += red[i];
    float rs = rsqrtf(vtot * (1.0f / 1024.0f) + 1e-5f);

#pragma unroll
    for (int i = 0; i < 4; i++) {
        int col = tid + 256 * i;
        float o = (v[i] - mu) * rs * g[col] + bb[col];
        size_t idx = (size_t)row * DIMV + col;
        hout[idx] = o;
        __nv_bfloat16 h = __float2bfloat16(o);
        Ohi[idx] = h;
        Olo[idx] = __float2bfloat16(o - __bfloat162float(h));
    }
}

// ---------------------------------------------------------------------------
// Host
// ---------------------------------------------------------------------------
extern "C" void kernel_launch(void* const* d_in, const int* in_sizes, int n_in,
                              void* d_out, int out_size)
{
    const float* x      = (const float*)d_in[0];
    const int*   qw     = (const int*)d_in[1];
    const float* scales = (const float*)d_in[2];
    const float* bias   = (const float*)d_in[3];
    const float* la     = (const float*)d_in[4];
    const float* lb     = (const float*)d_in[5];
    const float* lng    = (const float*)d_in[6];
    const float* lnb    = (const float*)d_in[7];
    float* out = (float*)d_out;

    void* p;
    cudaGetSymbolAddress(&p, g_Whi);  __nv_bfloat16* Whi  = (__nv_bfloat16*)p;
    cudaGetSymbolAddress(&p, g_Wlo);  __nv_bfloat16* Wlo  = (__nv_bfloat16*)p;
    cudaGetSymbolAddress(&p, g_ahi0); __nv_bfloat16* Ahi0 = (__nv_bfloat16*)p;
    cudaGetSymbolAddress(&p, g_alo0); __nv_bfloat16* Alo0 = (__nv_bfloat16*)p;
    cudaGetSymbolAddress(&p, g_ahi1); __nv_bfloat16* Ahi1 = (__nv_bfloat16*)p;
    cudaGetSymbolAddress(&p, g_alo1); __nv_bfloat16* Alo1 = (__nv_bfloat16*)p;
    cudaGetSymbolAddress(&p, g_ybuf); float* Ybuf = (float*)p;
    cudaGetSymbolAddress(&p, g_h);    float* Hbuf = (float*)p;

    __nv_bfloat16* ahi[2] = {Ahi0, Ahi1};
    __nv_bfloat16* alo[2] = {Alo0, Alo1};

    cudaFuncSetAttribute(gemm_kernel,
                         cudaFuncAttributeMaxDynamicSharedMemorySize, SMEM_TOTAL);

    prep_w_kernel<<<dim3(16, 16, NL), 256>>>(qw, scales, la, lb, Whi, Wlo);
    split_x_kernel<<<(BV * DIMV) / 256, 256>>>(x, ahi[0], alo[0]);

    for (int l = 0; l < NL; l++) {
        int ib = l & 1, ob = (l + 1) & 1;
        const __nv_bfloat16* wh = Whi + (size_t)l * DIMV * DIMV;
        const __nv_bfloat16* wl = Wlo + (size_t)l * DIMV * DIMV;
        const float* bl = bias + (size_t)l * DIMV;

        if (l % 3 != 2) {
            gemm_kernel<<<dim3(DIMV / TN, BV / TM), NTHR, SMEM_TOTAL>>>(
                ahi[ib], alo[ib], wh, wl, bl, 0, nullptr, nullptr,
                ahi[ob], alo[ob]);
        } else {
            const float* hin = (l == 2) ? x : Hbuf;
            float* fo = (l == NL - 1) ? out : Ybuf;
            gemm_kernel<<<dim3(DIMV / TN, BV / TM), NTHR, SMEM_TOTAL>>>(
                ahi[ib], alo[ib], wh, wl, bl, 1, hin, fo, nullptr, nullptr);
            if (l != NL - 1) {
                int blk = l / 3;
                ln_kernel<<<BV, 256>>>(Ybuf, lng + (size_t)blk * DIMV,
                                       lnb + (size_t)blk * DIMV, Hbuf,
                                       ahi[ob], alo[ob]);
            }
        }
    }
}

// round 9
// speedup vs baseline: 1.2914x; 1.0444x over previous
#include <cuda_runtime.h>
#include <cuda_bf16.h>
#include <cstdint>
#include <cstddef>

// ---------------------------------------------------------------------------
// QLoRABigNet, mma.sync path (tcgen05 unavailable at compute_103 PTX target).
// 18 layers of y = x @ W_eff^T + bias (+relu / +residual / LN).
// W_eff = dequant_int4 + lora_b@lora_a precomputed; split-bf16 3-MMA numerics.
// R9: R8 mbarrier ring with the deadlock fix: cp.async.mbarrier.arrive.NOINC
//     (default variant self-increments pending count -> barrier never flips).
//     4 stages x K=16, CTA 128x128, 256 thr, 2 CTAs/SM.
// ---------------------------------------------------------------------------

#define NL    18
#define DIMV  1024
#define BV    32768
#define NGRP  64

#define TM 128
#define TN 128
#define KC16 16
#define NC (DIMV / KC16)         // 64 chunks
#define NSTAGE 4
#define NTHR 256

#define ROWB 48                  // 32B data + 16B pad, conflict-free ldsm
#define OFF_AHI 0
#define OFF_ALO 6144             // 128*48
#define OFF_BHI 12288
#define OFF_BLO 18432
#define STAGE_BYTES 24576
#define MB_BASE (NSTAGE * STAGE_BYTES)      // 98304
#define SMEM_TOTAL (MB_BASE + 128)          // 98432 -> 2 CTAs/SM

// ---- scratch (device globals: allocation-free contract) --------------------
__device__ __nv_bfloat16 g_Whi[(size_t)NL * DIMV * DIMV];
__device__ __nv_bfloat16 g_Wlo[(size_t)NL * DIMV * DIMV];
__device__ __nv_bfloat16 g_ahi0[(size_t)BV * DIMV];
__device__ __nv_bfloat16 g_alo0[(size_t)BV * DIMV];
__device__ __nv_bfloat16 g_ahi1[(size_t)BV * DIMV];
__device__ __nv_bfloat16 g_alo1[(size_t)BV * DIMV];
__device__ float         g_ybuf[(size_t)BV * DIMV];
__device__ float         g_h[(size_t)BV * DIMV];

// ---------------------------------------------------------------------------
// PTX helpers
// ---------------------------------------------------------------------------
__device__ __forceinline__ void ldsm4(uint32_t* r, uint32_t a) {
    asm volatile("ldmatrix.sync.aligned.m8n8.x4.shared.b16 {%0,%1,%2,%3}, [%4];\n"
                 : "=r"(r[0]), "=r"(r[1]), "=r"(r[2]), "=r"(r[3]) : "r"(a));
}
__device__ __forceinline__ void mma16816(float* c, const uint32_t* a, const uint32_t* b) {
    asm volatile(
        "mma.sync.aligned.m16n8k16.row.col.f32.bf16.bf16.f32 "
        "{%0,%1,%2,%3}, {%4,%5,%6,%7}, {%8,%9}, {%0,%1,%2,%3};\n"
        : "+f"(c[0]), "+f"(c[1]), "+f"(c[2]), "+f"(c[3])
        : "r"(a[0]), "r"(a[1]), "r"(a[2]), "r"(a[3]), "r"(b[0]), "r"(b[1]));
}
__device__ __forceinline__ void cpa16(uint32_t dst, const void* src) {
    asm volatile("cp.async.cg.shared.global [%0], [%1], 16;" :: "r"(dst), "l"(src));
}
__device__ __forceinline__ void mbar_init(uint32_t addr, uint32_t cnt) {
    asm volatile("mbarrier.init.shared.b64 [%0], %1;" :: "r"(addr), "r"(cnt) : "memory");
}
__device__ __forceinline__ void mbar_arrive(uint32_t addr) {
    asm volatile("mbarrier.arrive.shared.b64 _, [%0];" :: "r"(addr) : "memory");
}
__device__ __forceinline__ void cp_arrive_noinc(uint32_t addr) {
    // NOINC: consume one of the preset expected arrivals when this thread's
    // prior cp.asyncs complete. (Default variant self-increments -> deadlock.)
    asm volatile("cp.async.mbarrier.arrive.noinc.shared.b64 [%0];" :: "r"(addr) : "memory");
}
__device__ __forceinline__ void mbar_wait(uint32_t addr, uint32_t parity) {
    asm volatile(
        "{\n .reg .pred P;\n"
        "W%=:\n mbarrier.try_wait.parity.acquire.cta.shared::cta.b64 P, [%0], %1, 0x989680;\n"
        " @P bra D%=;\n bra W%=;\nD%=:\n}"
        :: "r"(addr), "r"(parity) : "memory");
}

// ---------------------------------------------------------------------------
// Prepass: W_eff = qw*scale + B@A, split bf16 hi/lo. (validated R3/R5-R7)
// ---------------------------------------------------------------------------
__global__ __launch_bounds__(256) void prep_w_kernel(
    const int* __restrict__ qw, const float* __restrict__ sc,
    const float* __restrict__ la, const float* __restrict__ lb,
    __nv_bfloat16* __restrict__ Whi, __nv_bfloat16* __restrict__ Wlo)
{
    int l  = blockIdx.z;
    int o0 = blockIdx.y * 64;
    int k0 = blockIdx.x * 64;
    int tid = threadIdx.x;

    __shared__ float sLb[64][32];
    __shared__ float sLa[32][64];

    const float* lbp = lb + (size_t)l * DIMV * 32;
    const float* lap = la + (size_t)l * 32 * DIMV;

#pragma unroll
    for (int i = 0; i < 8; i++) {
        int off = tid + i * 256;
        int o = off >> 5, r = off & 31;
        sLb[o][r] = lbp[(size_t)(o0 + o) * 32 + r];
        int r2 = off >> 6, k = off & 63;
        sLa[r2][k] = lap[(size_t)r2 * DIMV + k0 + k];
    }
    __syncthreads();

    int to = tid >> 4, tk = tid & 15;
    float m[4][4];
#pragma unroll
    for (int i = 0; i < 4; i++)
#pragma unroll
        for (int j = 0; j < 4; j++) m[i][j] = 0.f;

#pragma unroll 8
    for (int r = 0; r < 32; r++) {
        float av[4], bv[4];
#pragma unroll
        for (int j = 0; j < 4; j++) av[j] = sLa[r][tk * 4 + j];
#pragma unroll
        for (int i = 0; i < 4; i++) bv[i] = sLb[to * 4 + i][r];
#pragma unroll
        for (int i = 0; i < 4; i++)
#pragma unroll
            for (int j = 0; j < 4; j++) m[i][j] += bv[i] * av[j];
    }

#pragma unroll
    for (int i = 0; i < 4; i++) {
        int o = o0 + to * 4 + i;
        const int*   qrow = qw + ((size_t)l * DIMV + o) * DIMV + k0;
        const float* srow = sc + ((size_t)l * DIMV + o) * NGRP;
#pragma unroll
        for (int j = 0; j < 4; j++) {
            int k = k0 + tk * 4 + j;
            float wv = (float)qrow[tk * 4 + j] * srow[k >> 4] + m[i][j];
            size_t idx = ((size_t)l * DIMV + o) * DIMV + k;
            __nv_bfloat16 h = __float2bfloat16(wv);
            Whi[idx] = h;
            Wlo[idx] = __float2bfloat16(wv - __bfloat162float(h));
        }
    }
}

__global__ __launch_bounds__(256) void split_x_kernel(
    const float* __restrict__ x, __nv_bfloat16* __restrict__ hi,
    __nv_bfloat16* __restrict__ lo)
{
    size_t i = (size_t)blockIdx.x * 256 + threadIdx.x;
    float v = x[i];
    __nv_bfloat16 h = __float2bfloat16(v);
    hi[i] = h;
    lo[i] = __float2bfloat16(v - __bfloat162float(h));
}

// ---------------------------------------------------------------------------
// GEMM: C[BV,DIMV] = X @ W^T. grid (8, 256), 256 threads, 8 warps (2x4),
// warp tile 64x32. mbarrier 4-stage ring over K=16 chunks, 2 CTAs/SM.
// mode 0: out = relu(acc+bias) -> bf16 hi/lo ; mode 1: out = acc+bias+hin fp32
// ---------------------------------------------------------------------------
__device__ __forceinline__ void load_stage(
    uint32_t sb, int s, int c, int tid, int m0, int n0,
    const __nv_bfloat16* __restrict__ Xhi, const __nv_bfloat16* __restrict__ Xlo,
    const __nv_bfloat16* __restrict__ Whi, const __nv_bfloat16* __restrict__ Wlo)
{
    const uint32_t st = sb + (uint32_t)s * STAGE_BYTES;
    const int kbase = c * KC16;
    const int row = tid >> 1, seg = tid & 1;
    const uint32_t off = (uint32_t)(row * ROWB + seg * 16);
    const size_t ga = (size_t)(m0 + row) * DIMV + kbase + seg * 8;
    cpa16(st + OFF_AHI + off, Xhi + ga);
    cpa16(st + OFF_ALO + off, Xlo + ga);
    const size_t gb = (size_t)(n0 + row) * DIMV + kbase + seg * 8;
    cpa16(st + OFF_BHI + off, Whi + gb);
    cpa16(st + OFF_BLO + off, Wlo + gb);
    // signal full[s] when this thread's copies land (expected count = 256)
    cp_arrive_noinc(sb + MB_BASE + (uint32_t)s * 16);
}

__global__ __launch_bounds__(NTHR, 2) void gemm_kernel(
    const __nv_bfloat16* __restrict__ Xhi, const __nv_bfloat16* __restrict__ Xlo,
    const __nv_bfloat16* __restrict__ Whi, const __nv_bfloat16* __restrict__ Wlo,
    const float* __restrict__ bias, int mode,
    const float* __restrict__ hin, float* __restrict__ fout,
    __nv_bfloat16* __restrict__ Ohi, __nv_bfloat16* __restrict__ Olo)
{
    extern __shared__ __align__(128) char smem[];
    const uint32_t sb = (uint32_t)__cvta_generic_to_shared(smem);

    const int tid = threadIdx.x, warp = tid >> 5, lane = tid & 31;
    const int wm = warp >> 2, wn = warp & 3;         // 2 x 4 warp grid, 64x32 tile
    const int m0 = blockIdx.y * TM, n0 = blockIdx.x * TN;

    // barriers: full[s] at MB_BASE + s*16, empty[s] at +8
    if (tid == 0) {
#pragma unroll
        for (int s = 0; s < NSTAGE; s++) {
            mbar_init(sb + MB_BASE + s * 16, NTHR);  // full: one noinc-arrive per thread
            mbar_init(sb + MB_BASE + s * 16 + 8, 8); // empty: one arrive per warp
        }
    }
    __syncthreads();

    // ldmatrix per-lane addressing (bytes, relative to stage base)
    const int mi = lane >> 3, rr = lane & 7;
    const uint32_t a_base = (uint32_t)((wm * 64 + (mi & 1) * 8 + rr) * ROWB
                                       + ((mi >> 1) * 8) * 2);
    const uint32_t b_base = (uint32_t)((wn * 32 + ((lane >> 4) << 3) + (lane & 7)) * ROWB
                                       + (((lane >> 3) & 1) * 8) * 2);

    // prologue: produce chunks 0,1 into stages 0,1 (produce-ahead distance 2)
    load_stage(sb, 0, 0, tid, m0, n0, Xhi, Xlo, Whi, Wlo);
    load_stage(sb, 1, 1, tid, m0, n0, Xhi, Xlo, Whi, Wlo);

    float acc[4][4][4];
#pragma unroll
    for (int i = 0; i < 4; i++)
#pragma unroll
        for (int j = 0; j < 4; j++)
#pragma unroll
            for (int q = 0; q < 4; q++) acc[i][j][q] = 0.f;

#pragma unroll 4
    for (int c = 0; c < NC; ++c) {
        // produce chunk c+2 (stage (c+2)%4): WAR-gated on consumption of c-2
        const int pc = c + 2;
        if (pc < NC) {
            const int ps = pc & 3, pj = pc >> 2;
            if (pj > 0)
                mbar_wait(sb + MB_BASE + (uint32_t)ps * 16 + 8, (pj - 1) & 1);
            load_stage(sb, ps, pc, tid, m0, n0, Xhi, Xlo, Whi, Wlo);
        }

        // consume chunk c
        const int s = c & 3, j = c >> 2;
        mbar_wait(sb + MB_BASE + (uint32_t)s * 16, j & 1);
        const uint32_t st = sb + (uint32_t)s * STAGE_BYTES;

        uint32_t wh[8], wl[8];
#pragma unroll
        for (int nfp = 0; nfp < 2; nfp++) {
            uint32_t bo = b_base + (uint32_t)(nfp * 16 * ROWB);
            ldsm4(wh + 4 * nfp, st + OFF_BHI + bo);
            ldsm4(wl + 4 * nfp, st + OFF_BLO + bo);
        }
        uint32_t fxh[4][4], fxl[4][4];
#pragma unroll
        for (int mf = 0; mf < 4; mf++) {
            uint32_t ao = a_base + (uint32_t)(mf * 16 * ROWB);
            ldsm4(fxh[mf], st + OFF_AHI + ao);
            ldsm4(fxl[mf], st + OFF_ALO + ao);
        }
        // buffer free for refill as soon as fragments are in registers
        // (mbarrier.arrive has release.cta semantics -> orders prior LDS)
        if (lane == 0)
            mbar_arrive(sb + MB_BASE + (uint32_t)s * 16 + 8);

        // term-major: 16 independent HMMAs per pass
#pragma unroll
        for (int mf = 0; mf < 4; mf++)
#pragma unroll
            for (int nf = 0; nf < 4; nf++)
                mma16816(acc[mf][nf], fxh[mf], wh + 2 * nf);
#pragma unroll
        for (int mf = 0; mf < 4; mf++)
#pragma unroll
            for (int nf = 0; nf < 4; nf++)
                mma16816(acc[mf][nf], fxl[mf], wh + 2 * nf);
#pragma unroll
        for (int mf = 0; mf < 4; mf++)
#pragma unroll
            for (int nf = 0; nf < 4; nf++)
                mma16816(acc[mf][nf], fxh[mf], wl + 2 * nf);
    }

    // epilogue
#pragma unroll
    for (int mf = 0; mf < 4; mf++) {
#pragma unroll
        for (int nf = 0; nf < 4; nf++) {
            const float* c = acc[mf][nf];
            int row0 = m0 + wm * 64 + mf * 16 + (lane >> 2);
            int row1 = row0 + 8;
            int n = n0 + wn * 32 + nf * 8 + 2 * (lane & 3);
            float bn0 = bias[n], bn1 = bias[n + 1];
            size_t o0 = (size_t)row0 * DIMV + n;
            size_t o1 = (size_t)row1 * DIMV + n;
            if (mode == 0) {
                float v00 = fmaxf(c[0] + bn0, 0.f), v01 = fmaxf(c[1] + bn1, 0.f);
                float v10 = fmaxf(c[2] + bn0, 0.f), v11 = fmaxf(c[3] + bn1, 0.f);
                __nv_bfloat162 h2, l2;
                h2.x = __float2bfloat16(v00); l2.x = __float2bfloat16(v00 - __bfloat162float(h2.x));
                h2.y = __float2bfloat16(v01); l2.y = __float2bfloat16(v01 - __bfloat162float(h2.y));
                *(__nv_bfloat162*)(Ohi + o0) = h2;
                *(__nv_bfloat162*)(Olo + o0) = l2;
                h2.x = __float2bfloat16(v10); l2.x = __float2bfloat16(v10 - __bfloat162float(h2.x));
                h2.y = __float2bfloat16(v11); l2.y = __float2bfloat16(v11 - __bfloat162float(h2.y));
                *(__nv_bfloat162*)(Ohi + o1) = h2;
                *(__nv_bfloat162*)(Olo + o1) = l2;
            } else {
                float2 hv0 = *(const float2*)(hin + o0);
                float2 hv1 = *(const float2*)(hin + o1);
                float2 r0v; r0v.x = c[0] + bn0 + hv0.x; r0v.y = c[1] + bn1 + hv0.y;
                float2 r1v; r1v.x = c[2] + bn0 + hv1.x; r1v.y = c[3] + bn1 + hv1.y;
                *(float2*)(fout + o0) = r0v;
                *(float2*)(fout + o1) = r1v;
            }
        }
    }
}

// ---------------------------------------------------------------------------
// LayerNorm (validated R3/R5-R7)
// ---------------------------------------------------------------------------
__global__ __launch_bounds__(256) void ln_kernel(
    const float* __restrict__ t, const float* __restrict__ g,
    const float* __restrict__ bb, float* __restrict__ hout,
    __nv_bfloat16* __restrict__ Ohi, __nv_bfloat16* __restrict__ Olo)
{
    int row = blockIdx.x;
    int tid = threadIdx.x;
    const float* tr = t + (size_t)row * DIMV;

    float v[4];
#pragma unroll
    for (int i = 0; i < 4; i++) v[i] = tr[tid + 256 * i];

    float s = v[0] + v[1] + v[2] + v[3];
#pragma unroll
    for (int o = 16; o > 0; o >>= 1) s += __shfl_xor_sync(0xffffffffu, s, o);

    __shared__ float red[8];
    int w = tid >> 5, ln = tid & 31;
    if (ln == 0) red[w] = s;
    __syncthreads();
    float tot = 0.f;
#pragma unroll
    for (int i = 0; i < 8; i++) tot += red[i];
    float mu = tot * (1.0f / 1024.0f);

    float sq = 0.f;
#pragma unroll
    for (int i = 0; i < 4; i++) { float d = v[i] - mu; sq += d * d; }
#pragma unroll
    for (int o = 16; o > 0; o >>= 1) sq += __shfl_xor_sync(0xffffffffu, sq, o);
    __syncthreads();
    if (ln == 0) red[w] = sq;
    __syncthreads();
    float vtot = 0.f;
#pragma unroll
    for (int i = 0; i < 8; i++) vtot += red[i];
    float rs = rsqrtf(vtot * (1.0f / 1024.0f) + 1e-5f);

#pragma unroll
    for (int i = 0; i < 4; i++) {
        int col = tid + 256 * i;
        float o = (v[i] - mu) * rs * g[col] + bb[col];
        size_t idx = (size_t)row * DIMV + col;
        hout[idx] = o;
        __nv_bfloat16 h = __float2bfloat16(o);
        Ohi[idx] = h;
        Olo[idx] = __float2bfloat16(o - __bfloat162float(h));
    }
}

// ---------------------------------------------------------------------------
// Host
// ---------------------------------------------------------------------------
extern "C" void kernel_launch(void* const* d_in, const int* in_sizes, int n_in,
                              void* d_out, int out_size)
{
    const float* x      = (const float*)d_in[0];
    const int*   qw     = (const int*)d_in[1];
    const float* scales = (const float*)d_in[2];
    const float* bias   = (const float*)d_in[3];
    const float* la     = (const float*)d_in[4];
    const float* lb     = (const float*)d_in[5];
    const float* lng    = (const float*)d_in[6];
    const float* lnb    = (const float*)d_in[7];
    float* out = (float*)d_out;

    void* p;
    cudaGetSymbolAddress(&p, g_Whi);  __nv_bfloat16* Whi  = (__nv_bfloat16*)p;
    cudaGetSymbolAddress(&p, g_Wlo);  __nv_bfloat16* Wlo  = (__nv_bfloat16*)p;
    cudaGetSymbolAddress(&p, g_ahi0); __nv_bfloat16* Ahi0 = (__nv_bfloat16*)p;
    cudaGetSymbolAddress(&p, g_alo0); __nv_bfloat16* Alo0 = (__nv_bfloat16*)p;
    cudaGetSymbolAddress(&p, g_ahi1); __nv_bfloat16* Ahi1 = (__nv_bfloat16*)p;
    cudaGetSymbolAddress(&p, g_alo1); __nv_bfloat16* Alo1 = (__nv_bfloat16*)p;
    cudaGetSymbolAddress(&p, g_ybuf); float* Ybuf = (float*)p;
    cudaGetSymbolAddress(&p, g_h);    float* Hbuf = (float*)p;

    __nv_bfloat16* ahi[2] = {Ahi0, Ahi1};
    __nv_bfloat16* alo[2] = {Alo0, Alo1};

    cudaFuncSetAttribute(gemm_kernel,
                         cudaFuncAttributeMaxDynamicSharedMemorySize, SMEM_TOTAL);

    prep_w_kernel<<<dim3(16, 16, NL), 256>>>(qw, scales, la, lb, Whi, Wlo);
    split_x_kernel<<<(BV * DIMV) / 256, 256>>>(x, ahi[0], alo[0]);

    for (int l = 0; l < NL; l++) {
        int ib = l & 1, ob = (l + 1) & 1;
        const __nv_bfloat16* wh = Whi + (size_t)l * DIMV * DIMV;
        const __nv_bfloat16* wl = Wlo + (size_t)l * DIMV * DIMV;
        const float* bl = bias + (size_t)l * DIMV;

        if (l % 3 != 2) {
            gemm_kernel<<<dim3(DIMV / TN, BV / TM), NTHR, SMEM_TOTAL>>>(
                ahi[ib], alo[ib], wh, wl, bl, 0, nullptr, nullptr,
                ahi[ob], alo[ob]);
        } else {
            const float* hin = (l == 2) ? x : Hbuf;
            float* fo = (l == NL - 1) ? out : Ybuf;
            gemm_kernel<<<dim3(DIMV / TN, BV / TM), NTHR, SMEM_TOTAL>>>(
                ahi[ib], alo[ib], wh, wl, bl, 1, hin, fo, nullptr, nullptr);
            if (l != NL - 1) {
                int blk = l / 3;
                ln_kernel<<<BV, 256>>>(Ybuf, lng + (size_t)blk * DIMV,
                                       lnb + (size_t)blk * DIMV, Hbuf,
                                       ahi[ob], alo[ob]);
            }
        }
    }
}